// round 9
// baseline (speedup 1.0000x reference)
#include <cuda_runtime.h>
#include <math.h>

// ---------------------------------------------------------------------------
// LLIE loss. B=16, C=3, H=W=512. SSIM 7x7 valid out 506x506.
// One fused launch interleaves 384 SSIM blocks (2 pairs x 48 planes x 2 col-
// halves x 2 row strips) with 1024 elementwise blocks so DRAM-bound elem work
// overlaps latency-bound SSIM work on every SM.
// ---------------------------------------------------------------------------

#define IMG_W   512
#define IMG_HW  (512 * 512)
#define OUT_W   506
#define NBC     48
#define N3      12582912.0
#define NHW     4194304.0

// 0 ssim0, 1 ssim1, 2 l1(all), 5 mse light, 6 mse out, 7 color, 8 gan
__device__ double g_acc[9];
__device__ unsigned int g_hist[NBC * 256];

// ---------------- f32x2 packed helpers (sm_103a) ---------------------------
typedef unsigned long long u64t;
__device__ __forceinline__ u64t f2_pack(float x, float y) {
    u64t r; asm("mov.b64 %0,{%1,%2};" : "=l"(r) : "f"(x), "f"(y)); return r;
}
__device__ __forceinline__ void f2_unpack(u64t p, float& x, float& y) {
    asm("mov.b64 {%0,%1},%2;" : "=f"(x), "=f"(y) : "l"(p));
}
__device__ __forceinline__ u64t f2_add(u64t a, u64t b) {
    u64t d; asm("add.rn.f32x2 %0,%1,%2;" : "=l"(d) : "l"(a), "l"(b)); return d;
}
__device__ __forceinline__ u64t f2_fma(u64t a, u64t b, u64t c) {
    u64t d; asm("fma.rn.f32x2 %0,%1,%2,%3;" : "=l"(d) : "l"(a), "l"(b), "l"(c)); return d;
}

// ---------------------------------------------------------------------------
__device__ __forceinline__ float blockReduceSum(float v, float* red) {
    #pragma unroll
    for (int o = 16; o > 0; o >>= 1) v += __shfl_down_sync(0xffffffffu, v, o);
    int lane = threadIdx.x & 31, wid = threadIdx.x >> 5;
    if (lane == 0) red[wid] = v;
    __syncthreads();
    v = (threadIdx.x < (blockDim.x >> 5)) ? red[threadIdx.x] : 0.f;
    if (wid == 0) {
        #pragma unroll
        for (int o = 16; o > 0; o >>= 1) v += __shfl_down_sync(0xffffffffu, v, o);
    }
    __syncthreads();
    return v;
}

// ---------------------------------------------------------------------------
__global__ void init_kernel() {
    int i = blockIdx.x * blockDim.x + threadIdx.x;
    if (i < 9) g_acc[i] = 0.0;
    for (int j = i; j < NBC * 256; j += gridDim.x * blockDim.x) g_hist[j] = 0u;
}

// ---------------------------------------------------------------------------
// SSIM block body (R8-proven): sliding vertical 7-row window with static
// register ring over (s,d)=(x+y,x-y) packed stats; 7-row smem groups with
// 2 barriers/group; 288 threads (256 compute cols + halo lanes in warp 8).
// sb in [0,384): cb = col half, strip = row strip of 253, pair & plane.
__device__ __forceinline__ void ssim_block(
    int sb, const float* __restrict__ x, const float* __restrict__ y,
    int which, u64t (*s)[264], float* red)
{
    const int tid = threadIdx.x;
    const int cb = sb & 1;
    const int strip = (sb >> 1) & 1;
    const int plane = sb >> 2;                 // 0..95 handled by caller split
    (void)plane;
    const int c0 = cb << 8;                    // 0 or 256
    const int R0 = strip * 253;                // output-row strip start
    const int total = 253 + 6;                 // 259 input rows (253*2 = 506)
    const int gc = c0 + tid;
    const bool loadok = (c0 == 0) ? (tid < 262) : (tid < 256);
    const bool compok = (tid < 256) && (gc < OUT_W);

    const float* xr = x + (long)R0 * IMG_W;
    const float* yr = y + (long)R0 * IMG_W;

    u64t rgA[7], rgQ[7];
    #pragma unroll
    for (int j = 0; j < 7; j++) { rgA[j] = 0ull; rgQ[j] = 0ull; }
    u64t SA = 0ull, SQ = 0ull;
    float local = 0.f;
    const u64t NEG1 = f2_pack(-1.f, -1.f);

    u64t ps[7];
    #pragma unroll
    for (int j = 0; j < 7; j++) {
        ps[j] = 0ull;
        if (loadok) {
            float xv = xr[(long)j * IMG_W + gc];
            float yv = yr[(long)j * IMG_W + gc];
            ps[j] = f2_pack(xv + yv, xv - yv);
        }
    }

    const int ngroups = (total + 6) / 7;       // 37
    for (int g = 0; g < ngroups; g++) {
        const int gr = g * 7;

        if (loadok) {
            #pragma unroll
            for (int j = 0; j < 7; j++)
                if (gr + j < total) s[j][tid] = ps[j];
        }
        __syncthreads();

        {
            const int nb = gr + 7;
            if (loadok && nb < total) {
                #pragma unroll
                for (int j = 0; j < 7; j++) {
                    const int rr = nb + j;
                    if (rr < total) {
                        float xv = xr[(long)rr * IMG_W + gc];
                        float yv = yr[(long)rr * IMG_W + gc];
                        ps[j] = f2_pack(xv + yv, xv - yv);
                    }
                }
            }
        }

        if (compok) {
            #pragma unroll
            for (int j = 0; j < 7; j++) {
                const int rr = gr + j;
                if (rr < total) {
                    u64t a = 0ull, q = 0ull;
                    #pragma unroll
                    for (int k = 0; k < 7; k++) {
                        u64t v = s[j][tid + k];
                        a = f2_add(a, v);
                        q = f2_fma(v, v, q);
                    }
                    SA = f2_add(SA, a); SA = f2_fma(rgA[j], NEG1, SA); rgA[j] = a;
                    SQ = f2_add(SQ, q); SQ = f2_fma(rgQ[j], NEG1, SQ); rgQ[j] = q;

                    if (rr >= 6) {
                        const float C1K = 0.4802f;      // 1e-4 * 2*49^2
                        const float C2K = 4.3218f;      // 9e-4 * 2*49^2
                        const float CV  = 49.f / 48.f;
                        const float CV49 = CV * 49.f;
                        float Ss, Sd, Qs, Qd;
                        f2_unpack(SA, Ss, Sd);
                        f2_unpack(SQ, Qs, Qd);
                        float ps2 = Ss * Ss, pd2 = Sd * Sd;
                        float t1 = ps2 - pd2, t2 = ps2 + pd2;
                        float q1 = Qs - Qd,  q2 = Qs + Qd;
                        float f1 = t1 + C1K;
                        float f3 = t2 + C1K;
                        float f2v = fmaf(CV49, q1, fmaf(-CV, t1, C2K));
                        float f4v = fmaf(CV49, q2, fmaf(-CV, t2, C2K));
                        local += __fdividef(f1 * f2v, f3 * f4v);
                    }
                }
            }
        }
        __syncthreads();
    }

    float tot = blockReduceSum(local, red);
    if (tid == 0) atomicAdd(&g_acc[which], (double)tot);
}

// ---------------------------------------------------------------------------
// Elementwise block body (R8-proven float4 path). eb in [0,1024).
// Threads >= 256 idle in the main loop (elem is DRAM-bound).
__device__ __forceinline__ void elem_block(
    int eb,
    const float4* __restrict__ img,   const float4* __restrict__ target,
    const float4* __restrict__ comp0, const float4* __restrict__ comp1,
    const float4* __restrict__ comp2, const float4* __restrict__ real0,
    const float4* __restrict__ real1,
    unsigned int* shist, float* red)
{
    const int tid = threadIdx.x;
    for (int i = tid; i < 768; i += 288) shist[i] = 0u;
    __syncthreads();

    const int b = eb >> 6;
    const int chunk = eb & 63;
    const int HW4 = IMG_HW / 4;
    const long bHW4 = (long)b * HW4;
    const long b3HW4 = (long)b * 3 * HW4;

    float s_l1 = 0.f, s_light = 0.f, s_mse = 0.f;

    if (tid < 256) {
        #pragma unroll
        for (int it = 0; it < 4; it++) {
            const int p = chunk * 1024 + it * 256 + tid;
            float4 r1v = real1[bHW4 + p];
            {
                float4 c2v = comp2[bHW4 + p];
                float d;
                d = c2v.x - r1v.x; s_light = fmaf(d, d, s_light);
                d = c2v.y - r1v.y; s_light = fmaf(d, d, s_light);
                d = c2v.z - r1v.z; s_light = fmaf(d, d, s_light);
                d = c2v.w - r1v.w; s_light = fmaf(d, d, s_light);
            }
            float4 c1v = comp1[bHW4 + p];
            #pragma unroll
            for (int c = 0; c < 3; c++) {
                const long idx = b3HW4 + (long)c * HW4 + p;
                float4 iv  = img[idx];
                float4 tv  = target[idx];
                float4 c0v = comp0[idx];
                float4 r0v = real0[idx];
                #define DO_COMP(ix, tx, c0x, r0x, c1x, r1x)                    \
                {                                                              \
                    s_l1 += fabsf((c0x) - (r0x))                               \
                          + fabsf((ix) - (c0x) * (c1x))                        \
                          + fabsf((tx) - (r0x) * (r1x));                       \
                    float d_ = (ix) - (tx); s_mse = fmaf(d_, d_, s_mse);       \
                    int bin_ = (int)rintf((tx) * 255.f);                       \
                    bin_ = min(max(bin_, 0), 255);                             \
                    atomicAdd(&shist[c * 256 + bin_], 1u);                     \
                }
                DO_COMP(iv.x, tv.x, c0v.x, r0v.x, c1v.x, r1v.x)
                DO_COMP(iv.y, tv.y, c0v.y, r0v.y, c1v.y, r1v.y)
                DO_COMP(iv.z, tv.z, c0v.z, r0v.z, c1v.z, r1v.z)
                DO_COMP(iv.w, tv.w, c0v.w, r0v.w, c1v.w, r1v.w)
                #undef DO_COMP
            }
        }
    }

    float t;
    t = blockReduceSum(s_l1, red);    if (tid == 0) atomicAdd(&g_acc[2], (double)t);
    t = blockReduceSum(s_light, red); if (tid == 0) atomicAdd(&g_acc[5], (double)t);
    t = blockReduceSum(s_mse, red);   if (tid == 0) atomicAdd(&g_acc[6], (double)t);

    __syncthreads();
    for (int i = tid; i < 768; i += 288)
        atomicAdd(&g_hist[b * 768 + i], shist[i]);
}

// ---------------------------------------------------------------------------
// Fused kernel: 1408 blocks. Per 11 consecutive block ids: 3 ssim + 8 elem
// (128 groups -> 384 ssim + 1024 elem), interleaving block types across SMs.
__global__ __launch_bounds__(288) void fused_kernel(
    const float* __restrict__ img,   const float* __restrict__ target,
    const float* __restrict__ comp0, const float* __restrict__ comp1,
    const float* __restrict__ comp2, const float* __restrict__ real0,
    const float* __restrict__ real1)
{
    __shared__ u64t s[7][264];
    __shared__ unsigned int shist[768];
    __shared__ float red[32];

    const int i = blockIdx.x;
    const int grp = i / 11;
    const int m = i - grp * 11;

    if (m < 3) {
        const int sb = grp * 3 + m;            // 0..383
        const int zz = sb >> 2;                // 0..95
        const int which = zz & 1;
        const int plane = zz >> 1;             // 0..47
        const long pbase = (long)plane * IMG_HW;
        const float* x = which ? img + pbase    : comp0 + pbase;
        const float* y = which ? target + pbase : real0 + pbase;
        ssim_block(sb, x, y, which, s, red);
    } else {
        const int eb = grp * 8 + (m - 3);      // 0..1023
        elem_block(eb, (const float4*)img, (const float4*)target,
                   (const float4*)comp0, (const float4*)comp1,
                   (const float4*)comp2, (const float4*)real0,
                   (const float4*)real1, shist, red);
    }
}

// ---------------------------------------------------------------------------
// Color L1 spread over 48 blocks (one per (b,c) plane) + GAN in block 0.
__global__ __launch_bounds__(256) void color_gan_kernel(
    const float* __restrict__ color_hist, const float* __restrict__ score)
{
    __shared__ float red[32];
    const float invHW = 1.f / (float)IMG_HW;
    const int bc = blockIdx.x;

    float cs = fabsf(color_hist[bc * 256 + threadIdx.x]
                     - (float)g_hist[bc * 256 + threadIdx.x] * invHW);

    float t = blockReduceSum(cs, red);
    if (threadIdx.x == 0) atomicAdd(&g_acc[7], (double)t);

    if (bc == 0) {
        float gs = 0.f;
        if (threadIdx.x < 16) {
            float zz = -score[threadIdx.x];
            gs = fmaxf(zz, 0.f) + log1pf(expf(-fabsf(zz)));
        }
        t = blockReduceSum(gs, red);
        if (threadIdx.x == 0) atomicAdd(&g_acc[8], (double)t);
    }
}

// ---------------------------------------------------------------------------
__global__ void finalize_kernel(float* out, int out_size) {
    if (threadIdx.x != 0 || blockIdx.x != 0) return;
    const double nS = 48.0 * 506.0 * 506.0;
    double ssim0 = g_acc[0] / nS;
    double ssim1 = g_acc[1] / nS;
    double r     = (1.0 - ssim0) + g_acc[2] / N3;
    double light = g_acc[5] / NHW;
    double color = g_acc[7] / (48.0 * 256.0);
    double outl  = (1.0 - ssim1) + g_acc[6] / N3;
    double gan   = g_acc[8] / 16.0;
    double loss  = r + light + 0.1 * color + outl + 0.05 * gan;

    float v[7] = {(float)loss, (float)loss, (float)r, (float)light,
                  (float)color, (float)outl, (float)gan};
    const float* src = (out_size == 6) ? (v + 1) : v;
    int n = out_size < 7 ? out_size : 7;
    for (int i = 0; i < n; i++) out[i] = src[i];
}

// ---------------------------------------------------------------------------
extern "C" void kernel_launch(void* const* d_in, const int* in_sizes, int n_in,
                              void* d_out, int out_size) {
    const float* img    = (const float*)d_in[0];
    const float* target = (const float*)d_in[1];
    const float* comp0  = (const float*)d_in[2];
    const float* comp1  = (const float*)d_in[3];
    const float* comp2  = (const float*)d_in[4];
    const float* real0  = (const float*)d_in[5];
    const float* real1  = (const float*)d_in[6];
    const float* chist  = (const float*)d_in[7];
    const float* score  = (const float*)d_in[8];
    float* out = (float*)d_out;

    init_kernel<<<48, 256>>>();

    fused_kernel<<<1408, 288>>>(img, target, comp0, comp1, comp2, real0, real1);

    color_gan_kernel<<<48, 256>>>(chist, score);

    finalize_kernel<<<1, 32>>>(out, out_size);
}

// round 10
// speedup vs baseline: 1.1726x; 1.1726x over previous
#include <cuda_runtime.h>
#include <math.h>

// ---------------------------------------------------------------------------
// LLIE loss: 2x SSIM(7x7, valid) + fused elementwise reductions + histogram
// color loss + BCE GAN loss.  B=16, C=3, H=W=512. SSIM valid out 506x506.
// ---------------------------------------------------------------------------

#define IMG_W   512
#define IMG_HW  (512 * 512)
#define OUT_W   506
#define NBC     48
#define N3      12582912.0
#define NHW     4194304.0

// 0 ssim0, 1 ssim1, 2 l1(all), 5 mse light, 6 mse out, 7 color, 8 gan
__device__ double g_acc[9];
__device__ unsigned int g_hist[NBC * 256];

// ---------------- f32x2 packed helpers (sm_103a) ---------------------------
typedef unsigned long long u64t;
__device__ __forceinline__ u64t f2_pack(float x, float y) {
    u64t r; asm("mov.b64 %0,{%1,%2};" : "=l"(r) : "f"(x), "f"(y)); return r;
}
__device__ __forceinline__ void f2_unpack(u64t p, float& x, float& y) {
    asm("mov.b64 {%0,%1},%2;" : "=f"(x), "=f"(y) : "l"(p));
}
__device__ __forceinline__ u64t f2_add(u64t a, u64t b) {
    u64t d; asm("add.rn.f32x2 %0,%1,%2;" : "=l"(d) : "l"(a), "l"(b)); return d;
}
__device__ __forceinline__ u64t f2_fma(u64t a, u64t b, u64t c) {
    u64t d; asm("fma.rn.f32x2 %0,%1,%2,%3;" : "=l"(d) : "l"(a), "l"(b), "l"(c)); return d;
}

// ---------------------------------------------------------------------------
__device__ __forceinline__ float blockReduceSum(float v, float* red) {
    #pragma unroll
    for (int o = 16; o > 0; o >>= 1) v += __shfl_down_sync(0xffffffffu, v, o);
    int lane = threadIdx.x & 31, wid = threadIdx.x >> 5;
    if (lane == 0) red[wid] = v;
    __syncthreads();
    v = (threadIdx.x < (blockDim.x >> 5)) ? red[threadIdx.x] : 0.f;
    if (wid == 0) {
        #pragma unroll
        for (int o = 16; o > 0; o >>= 1) v += __shfl_down_sync(0xffffffffu, v, o);
    }
    __syncthreads();
    return v;
}

// ---------------------------------------------------------------------------
__global__ void init_kernel() {
    int i = blockIdx.x * blockDim.x + threadIdx.x;
    if (i < 9) g_acc[i] = 0.0;
    for (int j = i; j < NBC * 256; j += gridDim.x * blockDim.x) g_hist[j] = 0u;
}

// ---------------------------------------------------------------------------
// Sliding-window SSIM, (s,d)=(x+y,x-y) packed stats, 7-row groups with
// DOUBLE-BUFFERED smem -> ONE barrier per group. Thread owns one column;
// vertical 7-row window as running sums with static register ring.
// Grid: (2 col-halves, 6 row strips of 85, 48 planes), 288 threads
// (256 compute cols + 6 halo-loader lanes in warp 8), 3 blocks/SM.
__global__ __launch_bounds__(288, 3) void ssim_kernel(
    const float* __restrict__ x, const float* __restrict__ y, int which)
{
    __shared__ u64t sbuf[2][7][264];
    __shared__ float red[32];

    const int tid = threadIdx.x;
    const int c0 = blockIdx.x << 8;            // 0 or 256
    const int R0 = blockIdx.y * 85;            // output-row strip start
    const int rows = min(85, OUT_W - R0);      // 85 or 81
    const int total = rows + 6;                // 91 or 87 input rows
    const long base = (long)blockIdx.z * IMG_HW;
    const int gc = c0 + tid;
    const bool loadok = (c0 == 0) ? (tid < 262) : (tid < 256);
    const bool compok = (tid < 256) && (gc < OUT_W);

    const float* xr = x + base + (long)R0 * IMG_W;
    const float* yr = y + base + (long)R0 * IMG_W;

    u64t rgA[7], rgQ[7];
    #pragma unroll
    for (int j = 0; j < 7; j++) { rgA[j] = 0ull; rgQ[j] = 0ull; }
    u64t SA = 0ull, SQ = 0ull;
    float local = 0.f;
    const u64t NEG1 = f2_pack(-1.f, -1.f);

    // prefetch group 0 (rows 0..6 always < total since total >= 87)
    u64t ps[7];
    #pragma unroll
    for (int j = 0; j < 7; j++) {
        ps[j] = 0ull;
        if (loadok) {
            float xv = xr[(long)j * IMG_W + gc];
            float yv = yr[(long)j * IMG_W + gc];
            ps[j] = f2_pack(xv + yv, xv - yv);
        }
    }

    const int ngroups = (total + 6) / 7;       // 13
    for (int g = 0; g < ngroups; g++) {
        const int gr = g * 7;
        const int buf = g & 1;

        // store current group into its buffer (other buffer may still be
        // in use by lagging warps; this one is free by the barrier of g-1)
        if (loadok) {
            #pragma unroll
            for (int j = 0; j < 7; j++)
                if (gr + j < total) sbuf[buf][j][tid] = ps[j];
        }
        __syncthreads();   // single barrier per group

        // prefetch next group into registers (overlaps compute below)
        {
            const int nb = gr + 7;
            if (loadok && nb < total) {
                #pragma unroll
                for (int j = 0; j < 7; j++) {
                    const int rr = nb + j;
                    if (rr < total) {
                        float xv = xr[(long)rr * IMG_W + gc];
                        float yv = yr[(long)rr * IMG_W + gc];
                        ps[j] = f2_pack(xv + yv, xv - yv);
                    }
                }
            }
        }

        // process 7 rows from this buffer
        if (compok) {
            #pragma unroll
            for (int j = 0; j < 7; j++) {
                const int rr = gr + j;
                if (rr < total) {
                    u64t v0 = sbuf[buf][j][tid + 0];
                    u64t v1 = sbuf[buf][j][tid + 1];
                    u64t v2 = sbuf[buf][j][tid + 2];
                    u64t v3 = sbuf[buf][j][tid + 3];
                    u64t v4 = sbuf[buf][j][tid + 4];
                    u64t v5 = sbuf[buf][j][tid + 5];
                    u64t v6 = sbuf[buf][j][tid + 6];
                    // tree-shaped sums: dep depth 3
                    u64t a01 = f2_add(v0, v1), a23 = f2_add(v2, v3);
                    u64t a45 = f2_add(v4, v5);
                    u64t a = f2_add(f2_add(a01, a23), f2_add(a45, v6));
                    u64t q01 = f2_fma(v1, v1, f2_fma(v0, v0, 0ull));
                    u64t q23 = f2_fma(v3, v3, f2_fma(v2, v2, 0ull));
                    u64t q45 = f2_fma(v5, v5, f2_fma(v4, v4, 0ull));
                    u64t q = f2_add(f2_add(q01, q23),
                                    f2_fma(v6, v6, q45));

                    SA = f2_add(SA, a); SA = f2_fma(rgA[j], NEG1, SA); rgA[j] = a;
                    SQ = f2_add(SQ, q); SQ = f2_fma(rgQ[j], NEG1, SQ); rgQ[j] = q;

                    if (rr >= 6) {
                        const float C1K = 0.4802f;      // 1e-4 * 2*49^2
                        const float C2K = 4.3218f;      // 9e-4 * 2*49^2
                        const float CV  = 49.f / 48.f;
                        const float CV49 = CV * 49.f;
                        float Ss, Sd, Qs, Qd;
                        f2_unpack(SA, Ss, Sd);
                        f2_unpack(SQ, Qs, Qd);
                        float ps2 = Ss * Ss, pd2 = Sd * Sd;
                        float t1 = ps2 - pd2, t2 = ps2 + pd2;
                        float q1 = Qs - Qd,  q2 = Qs + Qd;
                        float f1 = t1 + C1K;
                        float f3 = t2 + C1K;
                        float f2v = fmaf(CV49, q1, fmaf(-CV, t1, C2K));
                        float f4v = fmaf(CV49, q2, fmaf(-CV, t2, C2K));
                        local += __fdividef(f1 * f2v, f3 * f4v);
                    }
                }
            }
        }
    }

    float tot = blockReduceSum(local, red);
    if (tid == 0) atomicAdd(&g_acc[which], (double)tot);
}

// ---------------------------------------------------------------------------
// Fused elementwise pass, float4: merged-L1 + MSEs + target histogram.
// grid.x = B * 64; each block handles 4096 pixels.
__global__ __launch_bounds__(256, 4) void elem_kernel(
    const float4* __restrict__ img,   const float4* __restrict__ target,
    const float4* __restrict__ comp0, const float4* __restrict__ comp1,
    const float4* __restrict__ comp2, const float4* __restrict__ real0,
    const float4* __restrict__ real1)
{
    __shared__ unsigned int shist[768];
    __shared__ float red[32];

    const int tid = threadIdx.x;
    for (int i = tid; i < 768; i += 256) shist[i] = 0u;
    __syncthreads();

    const int b = blockIdx.x >> 6;
    const int chunk = blockIdx.x & 63;
    const int HW4 = IMG_HW / 4;
    const long bHW4 = (long)b * HW4;
    const long b3HW4 = (long)b * 3 * HW4;

    float s_l1 = 0.f, s_light = 0.f, s_mse = 0.f;

    #pragma unroll
    for (int it = 0; it < 4; it++) {
        const int p = chunk * 1024 + it * 256 + tid;
        float4 r1v = real1[bHW4 + p];
        {
            float4 c2v = comp2[bHW4 + p];
            float d;
            d = c2v.x - r1v.x; s_light = fmaf(d, d, s_light);
            d = c2v.y - r1v.y; s_light = fmaf(d, d, s_light);
            d = c2v.z - r1v.z; s_light = fmaf(d, d, s_light);
            d = c2v.w - r1v.w; s_light = fmaf(d, d, s_light);
        }
        float4 c1v = comp1[bHW4 + p];
        #pragma unroll
        for (int c = 0; c < 3; c++) {
            const long idx = b3HW4 + (long)c * HW4 + p;
            float4 iv  = img[idx];
            float4 tv  = target[idx];
            float4 c0v = comp0[idx];
            float4 r0v = real0[idx];
            #define DO_COMP(ix, tx, c0x, r0x, c1x, r1x)                        \
            {                                                                  \
                s_l1 += fabsf((c0x) - (r0x))                                   \
                      + fabsf((ix) - (c0x) * (c1x))                            \
                      + fabsf((tx) - (r0x) * (r1x));                           \
                float d_ = (ix) - (tx); s_mse = fmaf(d_, d_, s_mse);           \
                int bin_ = (int)rintf((tx) * 255.f);                           \
                bin_ = min(max(bin_, 0), 255);                                 \
                atomicAdd(&shist[c * 256 + bin_], 1u);                         \
            }
            DO_COMP(iv.x, tv.x, c0v.x, r0v.x, c1v.x, r1v.x)
            DO_COMP(iv.y, tv.y, c0v.y, r0v.y, c1v.y, r1v.y)
            DO_COMP(iv.z, tv.z, c0v.z, r0v.z, c1v.z, r1v.z)
            DO_COMP(iv.w, tv.w, c0v.w, r0v.w, c1v.w, r1v.w)
            #undef DO_COMP
        }
    }

    float t;
    t = blockReduceSum(s_l1, red);    if (tid == 0) atomicAdd(&g_acc[2], (double)t);
    t = blockReduceSum(s_light, red); if (tid == 0) atomicAdd(&g_acc[5], (double)t);
    t = blockReduceSum(s_mse, red);   if (tid == 0) atomicAdd(&g_acc[6], (double)t);

    __syncthreads();
    for (int i = tid; i < 768; i += 256)
        atomicAdd(&g_hist[b * 768 + i], shist[i]);
}

// ---------------------------------------------------------------------------
// Color L1 spread over 48 blocks (one per (b,c) plane) + GAN in block 0.
__global__ __launch_bounds__(256) void color_gan_kernel(
    const float* __restrict__ color_hist, const float* __restrict__ score)
{
    __shared__ float red[32];
    const float invHW = 1.f / (float)IMG_HW;
    const int bc = blockIdx.x;

    float cs = fabsf(color_hist[bc * 256 + threadIdx.x]
                     - (float)g_hist[bc * 256 + threadIdx.x] * invHW);

    float t = blockReduceSum(cs, red);
    if (threadIdx.x == 0) atomicAdd(&g_acc[7], (double)t);

    if (bc == 0) {
        float gs = 0.f;
        if (threadIdx.x < 16) {
            float zz = -score[threadIdx.x];
            gs = fmaxf(zz, 0.f) + log1pf(expf(-fabsf(zz)));
        }
        t = blockReduceSum(gs, red);
        if (threadIdx.x == 0) atomicAdd(&g_acc[8], (double)t);
    }
}

// ---------------------------------------------------------------------------
__global__ void finalize_kernel(float* out, int out_size) {
    if (threadIdx.x != 0 || blockIdx.x != 0) return;
    const double nS = 48.0 * 506.0 * 506.0;
    double ssim0 = g_acc[0] / nS;
    double ssim1 = g_acc[1] / nS;
    double r     = (1.0 - ssim0) + g_acc[2] / N3;
    double light = g_acc[5] / NHW;
    double color = g_acc[7] / (48.0 * 256.0);
    double outl  = (1.0 - ssim1) + g_acc[6] / N3;
    double gan   = g_acc[8] / 16.0;
    double loss  = r + light + 0.1 * color + outl + 0.05 * gan;

    float v[7] = {(float)loss, (float)loss, (float)r, (float)light,
                  (float)color, (float)outl, (float)gan};
    const float* src = (out_size == 6) ? (v + 1) : v;
    int n = out_size < 7 ? out_size : 7;
    for (int i = 0; i < n; i++) out[i] = src[i];
}

// ---------------------------------------------------------------------------
extern "C" void kernel_launch(void* const* d_in, const int* in_sizes, int n_in,
                              void* d_out, int out_size) {
    const float* img    = (const float*)d_in[0];
    const float* target = (const float*)d_in[1];
    const float* comp0  = (const float*)d_in[2];
    const float* comp1  = (const float*)d_in[3];
    const float* comp2  = (const float*)d_in[4];
    const float* real0  = (const float*)d_in[5];
    const float* real1  = (const float*)d_in[6];
    const float* chist  = (const float*)d_in[7];
    const float* score  = (const float*)d_in[8];
    float* out = (float*)d_out;

    init_kernel<<<48, 256>>>();

    dim3 sgrid(2, 6, NBC);
    ssim_kernel<<<sgrid, 288>>>(comp0, real0, 0);
    ssim_kernel<<<sgrid, 288>>>(img, target, 1);

    elem_kernel<<<16 * 64, 256>>>(
        (const float4*)img, (const float4*)target, (const float4*)comp0,
        (const float4*)comp1, (const float4*)comp2, (const float4*)real0,
        (const float4*)real1);

    color_gan_kernel<<<48, 256>>>(chist, score);

    finalize_kernel<<<1, 32>>>(out, out_size);
}

// round 12
// speedup vs baseline: 1.3458x; 1.1477x over previous
#include <cuda_runtime.h>
#include <math.h>

// ---------------------------------------------------------------------------
// LLIE loss: 2x SSIM(7x7, valid) + fused elementwise reductions + histogram
// color loss + BCE GAN loss.  B=16, C=3, H=W=512. SSIM valid out 506x506.
// The two SSIM launches and the elementwise launch run on FORKED capture
// streams so the DRAM-bound elem kernel overlaps the latency-bound SSIMs.
// Streams/events are created ONCE (first call = correctness run) so all
// stream-pool device memory is inside the harness's pre-capture baseline.
// ---------------------------------------------------------------------------

#define IMG_W   512
#define IMG_HW  (512 * 512)
#define OUT_W   506
#define NBC     48
#define N3      12582912.0
#define NHW     4194304.0

// 0 ssim0, 1 ssim1, 2 l1(all), 5 mse light, 6 mse out, 7 color, 8 gan
__device__ double g_acc[9];
__device__ unsigned int g_hist[NBC * 256];

// ---------------------------------------------------------------------------
__device__ __forceinline__ float blockReduceSum(float v, float* red) {
    #pragma unroll
    for (int o = 16; o > 0; o >>= 1) v += __shfl_down_sync(0xffffffffu, v, o);
    int lane = threadIdx.x & 31, wid = threadIdx.x >> 5;
    if (lane == 0) red[wid] = v;
    __syncthreads();
    v = (threadIdx.x < (blockDim.x >> 5)) ? red[threadIdx.x] : 0.f;
    if (wid == 0) {
        #pragma unroll
        for (int o = 16; o > 0; o >>= 1) v += __shfl_down_sync(0xffffffffu, v, o);
    }
    __syncthreads();
    return v;
}

// ---------------------------------------------------------------------------
__global__ void init_kernel() {
    int i = blockIdx.x * blockDim.x + threadIdx.x;
    if (i < 9) g_acc[i] = 0.0;
    for (int j = i; j < NBC * 256; j += gridDim.x * blockDim.x) g_hist[j] = 0u;
}

// ---------------------------------------------------------------------------
// Sliding-window SSIM (R3-proven body). Each thread owns one output column;
// vertical 7-row box sums kept as running sums in registers with a 7-deep
// register ring (row loop unrolled by 7 -> static ring indices). Horizontal
// 7-tap stats from one shared input row (double-buffered, 1 barrier/row);
// next row's globals prefetched into registers before the barrier.
// Grid: (2 col-blocks of 256 cols, 4 row strips of 127, 48 planes), 288 thr.
__global__ __launch_bounds__(288) void ssim_kernel(
    const float* __restrict__ x, const float* __restrict__ y, int which)
{
    __shared__ float2 s[2][264];
    __shared__ float red[32];

    const int tid = threadIdx.x;
    const int c0 = blockIdx.x << 8;            // 0 or 256
    const int R0 = blockIdx.y * 127;           // output-row strip start
    const int rows = min(127, OUT_W - R0);     // 127 or 125
    const int total = rows + 6;                // input rows this strip
    const long base = (long)blockIdx.z * IMG_HW;
    const int gc = c0 + tid;
    const bool loadok = (c0 == 0) ? (tid < 262) : (tid < 256);
    const bool compok = (tid < 256) && (gc < OUT_W);

    const float* xr = x + base + (long)R0 * IMG_W;
    const float* yr = y + base + (long)R0 * IMG_W;

    float rg[7][5];
    #pragma unroll
    for (int j = 0; j < 7; j++) {
        #pragma unroll
        for (int q = 0; q < 5; q++) rg[j][q] = 0.f;
    }
    float S0 = 0.f, S1 = 0.f, S2 = 0.f, S3 = 0.f, S4 = 0.f;
    float local = 0.f;

    // prefetch row 0
    float px = 0.f, py = 0.f;
    if (loadok) { px = xr[gc]; py = yr[gc]; }

    for (int rb = 0; rb < total; rb += 7) {
        #pragma unroll
        for (int j = 0; j < 7; j++) {
            const int r = rb + j;
            if (r < total) {
                const int buf = r & 1;
                if (loadok) s[buf][tid] = make_float2(px, py);
                if (r + 1 < total && loadok) {
                    const float* xn = xr + (long)(r + 1) * IMG_W;
                    const float* yn = yr + (long)(r + 1) * IMG_W;
                    px = xn[gc]; py = yn[gc];
                }
                __syncthreads();

                if (compok) {
                    float ax = 0.f, ay = 0.f, axx = 0.f, ayy = 0.f, axy = 0.f;
                    #pragma unroll
                    for (int k = 0; k < 7; k++) {
                        float2 v = s[buf][tid + k];
                        ax += v.x; ay += v.y;
                        axx = fmaf(v.x, v.x, axx);
                        ayy = fmaf(v.y, v.y, ayy);
                        axy = fmaf(v.x, v.y, axy);
                    }
                    S0 += ax  - rg[j][0]; rg[j][0] = ax;
                    S1 += ay  - rg[j][1]; rg[j][1] = ay;
                    S2 += axx - rg[j][2]; rg[j][2] = axx;
                    S3 += ayy - rg[j][3]; rg[j][3] = ayy;
                    S4 += axy - rg[j][4]; rg[j][4] = axy;

                    if (r >= 6) {
                        const float inv = 1.f / 49.f, COVN = 49.f / 48.f;
                        float ux = S0 * inv, uy = S1 * inv;
                        float uxx = S2 * inv, uyy = S3 * inv, uxy = S4 * inv;
                        float vx  = COVN * fmaf(-ux, ux, uxx);
                        float vy  = COVN * fmaf(-uy, uy, uyy);
                        float vxy = COVN * fmaf(-ux, uy, uxy);
                        float num = fmaf(ux + ux, uy, 1e-4f) *
                                    fmaf(2.f, vxy, 9e-4f);
                        float den = fmaf(ux, ux, fmaf(uy, uy, 1e-4f)) *
                                    (vx + vy + 9e-4f);
                        local += __fdividef(num, den);
                    }
                }
            }
        }
    }

    float tot = blockReduceSum(local, red);
    if (tid == 0) atomicAdd(&g_acc[which], (double)tot);
}

// ---------------------------------------------------------------------------
// Fused elementwise pass, float4: merged-L1 + MSEs + target histogram.
// grid.x = B * 64; each block handles 4096 pixels.
__global__ __launch_bounds__(256, 4) void elem_kernel(
    const float4* __restrict__ img,   const float4* __restrict__ target,
    const float4* __restrict__ comp0, const float4* __restrict__ comp1,
    const float4* __restrict__ comp2, const float4* __restrict__ real0,
    const float4* __restrict__ real1)
{
    __shared__ unsigned int shist[768];
    __shared__ float red[32];

    const int tid = threadIdx.x;
    for (int i = tid; i < 768; i += 256) shist[i] = 0u;
    __syncthreads();

    const int b = blockIdx.x >> 6;
    const int chunk = blockIdx.x & 63;
    const int HW4 = IMG_HW / 4;
    const long bHW4 = (long)b * HW4;
    const long b3HW4 = (long)b * 3 * HW4;

    float s_l1 = 0.f, s_light = 0.f, s_mse = 0.f;

    #pragma unroll
    for (int it = 0; it < 4; it++) {
        const int p = chunk * 1024 + it * 256 + tid;
        float4 r1v = real1[bHW4 + p];
        {
            float4 c2v = comp2[bHW4 + p];
            float d;
            d = c2v.x - r1v.x; s_light = fmaf(d, d, s_light);
            d = c2v.y - r1v.y; s_light = fmaf(d, d, s_light);
            d = c2v.z - r1v.z; s_light = fmaf(d, d, s_light);
            d = c2v.w - r1v.w; s_light = fmaf(d, d, s_light);
        }
        float4 c1v = comp1[bHW4 + p];
        #pragma unroll
        for (int c = 0; c < 3; c++) {
            const long idx = b3HW4 + (long)c * HW4 + p;
            float4 iv  = img[idx];
            float4 tv  = target[idx];
            float4 c0v = comp0[idx];
            float4 r0v = real0[idx];
            #define DO_COMP(ix, tx, c0x, r0x, c1x, r1x)                        \
            {                                                                  \
                s_l1 += fabsf((c0x) - (r0x))                                   \
                      + fabsf((ix) - (c0x) * (c1x))                            \
                      + fabsf((tx) - (r0x) * (r1x));                           \
                float d_ = (ix) - (tx); s_mse = fmaf(d_, d_, s_mse);           \
                int bin_ = (int)rintf((tx) * 255.f);                           \
                bin_ = min(max(bin_, 0), 255);                                 \
                atomicAdd(&shist[c * 256 + bin_], 1u);                         \
            }
            DO_COMP(iv.x, tv.x, c0v.x, r0v.x, c1v.x, r1v.x)
            DO_COMP(iv.y, tv.y, c0v.y, r0v.y, c1v.y, r1v.y)
            DO_COMP(iv.z, tv.z, c0v.z, r0v.z, c1v.z, r1v.z)
            DO_COMP(iv.w, tv.w, c0v.w, r0v.w, c1v.w, r1v.w)
            #undef DO_COMP
        }
    }

    float t;
    t = blockReduceSum(s_l1, red);    if (tid == 0) atomicAdd(&g_acc[2], (double)t);
    t = blockReduceSum(s_light, red); if (tid == 0) atomicAdd(&g_acc[5], (double)t);
    t = blockReduceSum(s_mse, red);   if (tid == 0) atomicAdd(&g_acc[6], (double)t);

    __syncthreads();
    for (int i = tid; i < 768; i += 256)
        atomicAdd(&g_hist[b * 768 + i], shist[i]);
}

// ---------------------------------------------------------------------------
// Color L1 spread over 48 blocks (one per (b,c) plane) + GAN in block 0.
__global__ __launch_bounds__(256) void color_gan_kernel(
    const float* __restrict__ color_hist, const float* __restrict__ score)
{
    __shared__ float red[32];
    const float invHW = 1.f / (float)IMG_HW;
    const int bc = blockIdx.x;

    float cs = fabsf(color_hist[bc * 256 + threadIdx.x]
                     - (float)g_hist[bc * 256 + threadIdx.x] * invHW);

    float t = blockReduceSum(cs, red);
    if (threadIdx.x == 0) atomicAdd(&g_acc[7], (double)t);

    if (bc == 0) {
        float gs = 0.f;
        if (threadIdx.x < 16) {
            float zz = -score[threadIdx.x];
            gs = fmaxf(zz, 0.f) + log1pf(expf(-fabsf(zz)));
        }
        t = blockReduceSum(gs, red);
        if (threadIdx.x == 0) atomicAdd(&g_acc[8], (double)t);
    }
}

// ---------------------------------------------------------------------------
__global__ void finalize_kernel(float* out, int out_size) {
    if (threadIdx.x != 0 || blockIdx.x != 0) return;
    const double nS = 48.0 * 506.0 * 506.0;
    double ssim0 = g_acc[0] / nS;
    double ssim1 = g_acc[1] / nS;
    double r     = (1.0 - ssim0) + g_acc[2] / N3;
    double light = g_acc[5] / NHW;
    double color = g_acc[7] / (48.0 * 256.0);
    double outl  = (1.0 - ssim1) + g_acc[6] / N3;
    double gan   = g_acc[8] / 16.0;
    double loss  = r + light + 0.1 * color + outl + 0.05 * gan;

    float v[7] = {(float)loss, (float)loss, (float)r, (float)light,
                  (float)color, (float)outl, (float)gan};
    const float* src = (out_size == 6) ? (v + 1) : v;
    int n = out_size < 7 ? out_size : 7;
    for (int i = 0; i < n; i++) out[i] = src[i];
}

// ---------------------------------------------------------------------------
// Side streams + fork/join events, created exactly once. First use happens
// during the harness's correctness run, so all lazily-allocated stream-pool
// device memory is part of the pre-capture baseline; NOTHING is created or
// freed during graph capture or replay. Work per call is identical.
struct SideStreams {
    cudaStream_t s1, s2;
    cudaEvent_t evF, ev1, ev2;
    SideStreams() {
        cudaStreamCreateWithFlags(&s1, cudaStreamNonBlocking);
        cudaStreamCreateWithFlags(&s2, cudaStreamNonBlocking);
        cudaEventCreateWithFlags(&evF, cudaEventDisableTiming);
        cudaEventCreateWithFlags(&ev1, cudaEventDisableTiming);
        cudaEventCreateWithFlags(&ev2, cudaEventDisableTiming);
    }
};

extern "C" void kernel_launch(void* const* d_in, const int* in_sizes, int n_in,
                              void* d_out, int out_size) {
    const float* img    = (const float*)d_in[0];
    const float* target = (const float*)d_in[1];
    const float* comp0  = (const float*)d_in[2];
    const float* comp1  = (const float*)d_in[3];
    const float* comp2  = (const float*)d_in[4];
    const float* real0  = (const float*)d_in[5];
    const float* real1  = (const float*)d_in[6];
    const float* chist  = (const float*)d_in[7];
    const float* score  = (const float*)d_in[8];
    float* out = (float*)d_out;

    static SideStreams ss;   // constructed on first call (correctness run)

    init_kernel<<<48, 256>>>();

    // fork: ssim0 -> s1, ssim1 -> s2; elem stays on the origin stream
    cudaEventRecord(ss.evF, 0);
    cudaStreamWaitEvent(ss.s1, ss.evF, 0);
    cudaStreamWaitEvent(ss.s2, ss.evF, 0);

    dim3 sgrid(2, 4, NBC);
    ssim_kernel<<<sgrid, 288, 0, ss.s1>>>(comp0, real0, 0);
    ssim_kernel<<<sgrid, 288, 0, ss.s2>>>(img, target, 1);

    elem_kernel<<<16 * 64, 256>>>(
        (const float4*)img, (const float4*)target, (const float4*)comp0,
        (const float4*)comp1, (const float4*)comp2, (const float4*)real0,
        (const float4*)real1);

    // join back onto the origin stream
    cudaEventRecord(ss.ev1, ss.s1);
    cudaEventRecord(ss.ev2, ss.s2);
    cudaStreamWaitEvent(0, ss.ev1, 0);
    cudaStreamWaitEvent(0, ss.ev2, 0);

    color_gan_kernel<<<48, 256>>>(chist, score);

    finalize_kernel<<<1, 32>>>(out, out_size);
}